// round 15
// baseline (speedup 1.0000x reference)
#include <cuda_runtime.h>
#include <cstdint>

// GlobalMixer: y[b,h,o,g] = sum_i W[h,o,i] * x[b,h,i,g]
//   x: (B=512, H=512, SEQ=256) fp32, SEQ elem (i,g) at i*16+g
//   W: (H=512, 16, 16) fp32
//
// R15: compose the two validated micro-levers — 64-thread CTAs (8 phases/
// SM, best synced variant R11) x warp-private W with __syncwarp only
// (best in-kernel R14). Every warp on the SM is now fully decoupled:
// no BAR, hoisted x loads, 16 independent warp-phases per SM. Logical
// endpoint of the startup-latency elimination series.
// Compute body unchanged: g-quad, unsplatted warp-private W, packed
// f32x2 FMA, streaming .cs loads/stores.

#define HIDDEN 512
#define BATCH  512
#define B_PER_BLOCK 16
#define THREADS 64

__device__ __forceinline__ unsigned long long fma2(unsigned long long a,
                                                   unsigned long long b,
                                                   unsigned long long c) {
    unsigned long long d;
    asm("fma.rn.f32x2 %0, %1, %2, %3;" : "=l"(d) : "l"(a), "l"(b), "l"(c));
    return d;
}

__device__ __forceinline__ unsigned long long splat2(float w) {
    unsigned long long d;
    asm("mov.b64 %0, {%1, %1};" : "=l"(d) : "f"(w));
    return d;
}

__global__ __launch_bounds__(THREADS, 8)
void global_mixer_kernel(const float* __restrict__ x,
                         const float* __restrict__ W,
                         float* __restrict__ y) {
    // Warp-private copies: ws[warp][256]; 2 KB per CTA
    __shared__ float ws[2][256];

    const int h    = blockIdx.x;            // 0..511
    const int b0   = blockIdx.y * B_PER_BLOCK;
    const int t    = threadIdx.x;           // 0..63
    const int warp = t >> 5;                // 0..1
    const int lane = t & 31;

    const int b_local = t >> 2;   // 0..15
    const int gq      = t & 3;    // g-quad -> g = 4*gq .. 4*gq+3

    const size_t base = ((size_t)(b0 + b_local) * HIDDEN + h) * 256 + gq * 4;
    const ulonglong2* __restrict__ xp =
        reinterpret_cast<const ulonglong2*>(x + base);
    ulonglong2* __restrict__ yp =
        reinterpret_cast<ulonglong2*>(y + base);

    // DRAM loads FIRST: overlap their latency with the W L2-load + STS
    ulonglong2 xv[16];
#pragma unroll
    for (int i = 0; i < 16; i++) xv[i] = __ldcs(xp + (size_t)i * 4);

    // Warp-private W stage (L2-resident); warp-level sync only — this
    // warp is fully decoupled from every other warp on the SM.
#pragma unroll
    for (int k = 0; k < 8; k++)
        ws[warp][lane + 32 * k] = W[h * 256 + lane + 32 * k];
    __syncwarp();

    const float* __restrict__ wbase = ws[warp];

#pragma unroll
    for (int o = 0; o < 16; o++) {
        unsigned long long alo = 0ull, ahi = 0ull;
        const float4* __restrict__ wrow =
            reinterpret_cast<const float4*>(wbase + o * 16);
#pragma unroll
        for (int i4 = 0; i4 < 4; i4++) {
            float4 w = wrow[i4];            // LDS.128 uniform -> broadcast
            unsigned long long w0 = splat2(w.x);
            unsigned long long w1 = splat2(w.y);
            unsigned long long w2 = splat2(w.z);
            unsigned long long w3 = splat2(w.w);
            alo = fma2(xv[4 * i4 + 0].x, w0, alo);
            ahi = fma2(xv[4 * i4 + 0].y, w0, ahi);
            alo = fma2(xv[4 * i4 + 1].x, w1, alo);
            ahi = fma2(xv[4 * i4 + 1].y, w1, ahi);
            alo = fma2(xv[4 * i4 + 2].x, w2, alo);
            ahi = fma2(xv[4 * i4 + 2].y, w2, ahi);
            alo = fma2(xv[4 * i4 + 3].x, w3, alo);
            ahi = fma2(xv[4 * i4 + 3].y, w3, ahi);
        }
        ulonglong2 out; out.x = alo; out.y = ahi;
        __stcs(yp + (size_t)o * 4, out);    // STG.128 streaming, coalesced
    }
}

extern "C" void kernel_launch(void* const* d_in, const int* in_sizes, int n_in,
                              void* d_out, int out_size) {
    const float* x = (const float*)d_in[0];   // 512*512*256 fp32
    const float* W = (const float*)d_in[1];   // 512*16*16 fp32
    float* y = (float*)d_out;

    dim3 grid(HIDDEN, BATCH / B_PER_BLOCK);   // (512, 32)
    global_mixer_kernel<<<grid, THREADS>>>(x, W, y);
}

// round 16
// speedup vs baseline: 1.1749x; 1.1749x over previous
#include <cuda_runtime.h>
#include <cstdint>

// GlobalMixer: y[b,h,o,g] = sum_i W[h,o,i] * x[b,h,i,g]
//   x: (B=512, H=512, SEQ=256) fp32, SEQ elem (i,g) at i*16+g
//   W: (H=512, 16, 16) fp32
//
// FINAL = R9 config (best verified harness: 82.0us, reproduced 82.5us;
// in-kernel ~77us = 536 MB @ ~7.0 TB/s effective, 88% of HBM spec on a
// 1:1 read/write stream).
//
// Design ledger (15 rounds):
//   validated: g-quad per thread (1 smem word per output float, keeps
//              L1 < 60%); unsplatted W in smem with register splat on the
//              idle ALU pipe; packed f32x2 FMA (PTX-only, halves FMA
//              issue); x-loads hoisted above the W/STS/BAR chain
//              (R8: -2.1us); 128-thread CTAs, 4 phases/SM (R9).
//   falsified: occupancy scaling (R4, R10), demand smoothness (R6),
//              DRAM address density (R7), multi-tile persistence
//              (R4, R12: reg-spill -> 2.2x traffic), 64t+warp-private
//              composition (R15: codegen pathology).
// Remaining gap to the 67us spec floor is HBM R/W turnaround physics.

#define HIDDEN 512
#define BATCH  512
#define B_PER_BLOCK 32
#define THREADS 128

__device__ __forceinline__ unsigned long long fma2(unsigned long long a,
                                                   unsigned long long b,
                                                   unsigned long long c) {
    unsigned long long d;
    asm("fma.rn.f32x2 %0, %1, %2, %3;" : "=l"(d) : "l"(a), "l"(b), "l"(c));
    return d;
}

__device__ __forceinline__ unsigned long long splat2(float w) {
    unsigned long long d;
    asm("mov.b64 %0, {%1, %1};" : "=l"(d) : "f"(w));
    return d;
}

__global__ __launch_bounds__(THREADS, 4)
void global_mixer_kernel(const float* __restrict__ x,
                         const float* __restrict__ W,
                         float* __restrict__ y) {
    __shared__ float ws[256];               // W[h] plain fp32, 1 KB

    const int h  = blockIdx.x;              // 0..511
    const int b0 = blockIdx.y * B_PER_BLOCK;
    const int t  = threadIdx.x;             // 0..127

    const int b_local = t >> 2;   // 0..31
    const int gq      = t & 3;    // g-quad -> g = 4*gq .. 4*gq+3

    const size_t base = ((size_t)(b0 + b_local) * HIDDEN + h) * 256 + gq * 4;
    const ulonglong2* __restrict__ xp =
        reinterpret_cast<const ulonglong2*>(x + base);
    ulonglong2* __restrict__ yp =
        reinterpret_cast<ulonglong2*>(y + base);

    // DRAM loads FIRST: overlap their latency with the W L2-load + STS + BAR
    ulonglong2 xv[16];
#pragma unroll
    for (int i = 0; i < 16; i++) xv[i] = __ldcs(xp + (size_t)i * 4);

    // W stage: 128 threads x 2 elements (L2-resident)
    ws[t]       = W[h * 256 + t];
    ws[t + 128] = W[h * 256 + t + 128];
    __syncthreads();

#pragma unroll
    for (int o = 0; o < 16; o++) {
        unsigned long long alo = 0ull, ahi = 0ull;
        const float4* __restrict__ wrow =
            reinterpret_cast<const float4*>(&ws[o * 16]);
#pragma unroll
        for (int i4 = 0; i4 < 4; i4++) {
            float4 w = wrow[i4];            // LDS.128: 4 distinct W values
            unsigned long long w0 = splat2(w.x);
            unsigned long long w1 = splat2(w.y);
            unsigned long long w2 = splat2(w.z);
            unsigned long long w3 = splat2(w.w);
            alo = fma2(xv[4 * i4 + 0].x, w0, alo);
            ahi = fma2(xv[4 * i4 + 0].y, w0, ahi);
            alo = fma2(xv[4 * i4 + 1].x, w1, alo);
            ahi = fma2(xv[4 * i4 + 1].y, w1, ahi);
            alo = fma2(xv[4 * i4 + 2].x, w2, alo);
            ahi = fma2(xv[4 * i4 + 2].y, w2, ahi);
            alo = fma2(xv[4 * i4 + 3].x, w3, alo);
            ahi = fma2(xv[4 * i4 + 3].y, w3, ahi);
        }
        ulonglong2 out; out.x = alo; out.y = ahi;
        __stcs(yp + (size_t)o * 4, out);    // STG.128 streaming, coalesced
    }
}

extern "C" void kernel_launch(void* const* d_in, const int* in_sizes, int n_in,
                              void* d_out, int out_size) {
    const float* x = (const float*)d_in[0];   // 512*512*256 fp32
    const float* W = (const float*)d_in[1];   // 512*16*16 fp32
    float* y = (float*)d_out;

    dim3 grid(HIDDEN, BATCH / B_PER_BLOCK);   // (512, 16)
    global_mixer_kernel<<<grid, THREADS>>>(x, W, y);
}

// round 17
// speedup vs baseline: 1.1795x; 1.0039x over previous
#include <cuda_runtime.h>
#include <cstdint>

// GlobalMixer: y[b,h,o,g] = sum_i W[h,o,i] * x[b,h,i,g]
//   x: (B=512, H=512, SEQ=256) fp32, SEQ elem (i,g) at i*16+g
//   W: (H=512, 16, 16) fp32
//
// FINAL (converged, triple-verified: 82.0/82.5/82.3us harness; in-kernel
// ~77us = 536 MB @ ~7.0 TB/s effective, 88% of HBM spec on a 1:1 R/W
// stream). Memory-bound; remaining gap to the 67us spec floor is HBM
// read/write turnaround physics.
//
// Design (16-round ledger):
//   - g-quad per thread: 1 smem word per output float keeps L1 < 60%
//     (L1 >= 80% was the binder in splatted variants: 102-105us).
//   - W unsplatted in smem; (w,w) packs built via mov.b64 on the idle
//     ALU pipe; LDS.128 delivers 4 distinct W values per access.
//   - packed fma.rn.f32x2 (PTX-only): halves FMA issue count.
//   - 16 x LDG.128 hoisted ABOVE the W-load/STS/BAR chain (-2.1us):
//     DRAM latency overlaps CTA startup.
//   - 128-thread CTAs, 4 independent phases/SM: store-tails interleave
//     with load-heads across CTAs.
//   - .cs streaming on x/y (touch-once), STG.128 coalesced.
// Falsified: occupancy scaling, demand smoothness, DRAM address density,
// multi-tile persistence (reg-spill), further desync compositions.

#define HIDDEN 512
#define BATCH  512
#define B_PER_BLOCK 32
#define THREADS 128

__device__ __forceinline__ unsigned long long fma2(unsigned long long a,
                                                   unsigned long long b,
                                                   unsigned long long c) {
    unsigned long long d;
    asm("fma.rn.f32x2 %0, %1, %2, %3;" : "=l"(d) : "l"(a), "l"(b), "l"(c));
    return d;
}

__device__ __forceinline__ unsigned long long splat2(float w) {
    unsigned long long d;
    asm("mov.b64 %0, {%1, %1};" : "=l"(d) : "f"(w));
    return d;
}

__global__ __launch_bounds__(THREADS, 4)
void global_mixer_kernel(const float* __restrict__ x,
                         const float* __restrict__ W,
                         float* __restrict__ y) {
    __shared__ float ws[256];               // W[h] plain fp32, 1 KB

    const int h  = blockIdx.x;              // 0..511
    const int b0 = blockIdx.y * B_PER_BLOCK;
    const int t  = threadIdx.x;             // 0..127

    const int b_local = t >> 2;   // 0..31
    const int gq      = t & 3;    // g-quad -> g = 4*gq .. 4*gq+3

    const size_t base = ((size_t)(b0 + b_local) * HIDDEN + h) * 256 + gq * 4;
    const ulonglong2* __restrict__ xp =
        reinterpret_cast<const ulonglong2*>(x + base);
    ulonglong2* __restrict__ yp =
        reinterpret_cast<ulonglong2*>(y + base);

    // DRAM loads FIRST: overlap their latency with the W L2-load + STS + BAR
    ulonglong2 xv[16];
#pragma unroll
    for (int i = 0; i < 16; i++) xv[i] = __ldcs(xp + (size_t)i * 4);

    // W stage: 128 threads x 2 elements (L2-resident)
    ws[t]       = W[h * 256 + t];
    ws[t + 128] = W[h * 256 + t + 128];
    __syncthreads();

#pragma unroll
    for (int o = 0; o < 16; o++) {
        unsigned long long alo = 0ull, ahi = 0ull;
        const float4* __restrict__ wrow =
            reinterpret_cast<const float4*>(&ws[o * 16]);
#pragma unroll
        for (int i4 = 0; i4 < 4; i4++) {
            float4 w = wrow[i4];            // LDS.128: 4 distinct W values
            unsigned long long w0 = splat2(w.x);
            unsigned long long w1 = splat2(w.y);
            unsigned long long w2 = splat2(w.z);
            unsigned long long w3 = splat2(w.w);
            alo = fma2(xv[4 * i4 + 0].x, w0, alo);
            ahi = fma2(xv[4 * i4 + 0].y, w0, ahi);
            alo = fma2(xv[4 * i4 + 1].x, w1, alo);
            ahi = fma2(xv[4 * i4 + 1].y, w1, ahi);
            alo = fma2(xv[4 * i4 + 2].x, w2, alo);
            ahi = fma2(xv[4 * i4 + 2].y, w2, ahi);
            alo = fma2(xv[4 * i4 + 3].x, w3, alo);
            ahi = fma2(xv[4 * i4 + 3].y, w3, ahi);
        }
        ulonglong2 out; out.x = alo; out.y = ahi;
        __stcs(yp + (size_t)o * 4, out);    // STG.128 streaming, coalesced
    }
}

extern "C" void kernel_launch(void* const* d_in, const int* in_sizes, int n_in,
                              void* d_out, int out_size) {
    const float* x = (const float*)d_in[0];   // 512*512*256 fp32
    const float* W = (const float*)d_in[1];   // 512*16*16 fp32
    float* y = (float*)d_out;

    dim3 grid(HIDDEN, BATCH / B_PER_BLOCK);   // (512, 16)
    global_mixer_kernel<<<grid, THREADS>>>(x, W, y);
}